// round 14
// baseline (speedup 1.0000x reference)
#include <cuda_runtime.h>
#include <cuda_fp16.h>
#include <math.h>

#define NV 2048
#define VV 4096           // 2*NV
#define BB 4
#define C0 64
#define HD 128
#define EE (5*NV)         // 10240 edges
#define NNZ (46*NV)       // 94208 memberships
#define XH2 (BB*NV*C0)    // modality-2 offset in g_xh

// ---------------- scratch (device globals; no allocation) ----------------
__device__ float  g_f[VV*C0];      // normalized batch-mean features (fp32)
__device__ __half g_xh[2*BB*NV*C0]; // raw input features (half copy)
__device__ float  g_sim[2][NV*NV];
__device__ int    g_knn1[NV*19];
__device__ int    g_knn2[NV*13];
__device__ int    g_dv[VV];
__device__ float  g_isdv[VV];
__device__ int    g_off[VV+1];
__device__ int    g_ctr[VV];
__device__ int    g_adj[NNZ];
__device__ float  g_u[VV*512];     // layer-2 aggregate (fp32)
__device__ __half g_yh[VV*512];    // layer-1 output (half)
__device__ __half g_z1h[EE*256];   // layer-1 edge features (half)
__device__ __half g_z2h[EE*512];   // layer-2 edge features (half)

__device__ __forceinline__ unsigned long long ffma2(unsigned long long a,
                                                    unsigned long long b,
                                                    unsigned long long c) {
    unsigned long long d;
    asm("fma.rn.f32x2 %0, %1, %2, %3;" : "=l"(d) : "l"(a), "l"(b), "l"(c));
    return d;
}
__device__ __forceinline__ float f2lo(unsigned long long x) {
    return __uint_as_float((unsigned)(x & 0xffffffffULL));
}
__device__ __forceinline__ float f2hi(unsigned long long x) {
    return __uint_as_float((unsigned)(x >> 32));
}
__device__ __forceinline__ float4 h4_to_f4(uint2 p) {
    __half2 h0 = *(__half2*)&p.x, h1 = *(__half2*)&p.y;
    float2 f0 = __half22float2(h0), f1 = __half22float2(h1);
    return make_float4(f0.x, f0.y, f1.x, f1.y);
}

// ---------------- kernels ----------------

// batch-mean + L2-normalize (fp32 out for sim) + fp16 raw copy + zero g_dv.
// warp per vertex. grid VV/8, block 256.
__global__ void k_meannorm2(const float* __restrict__ f1, const float* __restrict__ f2) {
    int warp = threadIdx.x >> 5, lane = threadIdx.x & 31;
    int v = blockIdx.x * 8 + warp;
    if (lane == 0) g_dv[v] = 0;
    const float* src; int n; int xoff;
    if (v < NV) { src = f1; n = v;      xoff = 0; }
    else        { src = f2; n = v - NV; xoff = XH2; }
    float m0 = 0.f, m1 = 0.f;
#pragma unroll
    for (int b = 0; b < BB; b++) {
        const float* row = src + (b*NV + n)*C0;
        float r0 = row[lane], r1 = row[lane + 32];
        m0 += r0; m1 += r1;
        g_xh[xoff + (b*NV + n)*C0 + lane]      = __float2half(r0);
        g_xh[xoff + (b*NV + n)*C0 + lane + 32] = __float2half(r1);
    }
    m0 *= 0.25f; m1 *= 0.25f;
    float ss = m0*m0 + m1*m1;
#pragma unroll
    for (int off = 16; off; off >>= 1)
        ss += __shfl_xor_sync(0xffffffffu, ss, off);
    float d = fmaxf(sqrtf(ss), 1e-12f);
    float inv = 1.0f / d;
    g_f[v*C0 + lane]      = m0 * inv;
    g_f[v*C0 + lane + 32] = m1 * inv;
}

// sim = F F^T, symmetric: upper-tri 128x128 block pairs only, fp32 FFMA2.
// mirror via smem transpose. grid (136,1,2), block 256.
#define SIM_SMEM ((64*264 + 64*132) * 4)
__global__ void k_sim2() {
    extern __shared__ float sm[];
    float* As = sm;               // [64][264] A rows duplicated pairwise
    float* Bs = sm + 64*264;      // [64][132]
    int modal = blockIdx.z;
    const float* __restrict__ f = g_f + modal*NV*C0;
    float* __restrict__ S = g_sim[modal];

    // decode upper-tri pair (by <= bx) from linear index
    int li = blockIdx.x, by = 0;
    while (li >= 16 - by) { li -= 16 - by; by++; }
    int bx = by + li;
    int r0 = by * 128, c0 = bx * 128;

    int tid = threadIdx.x;
    for (int i = tid; i < 128*64; i += 256) {
        int r = i >> 6, c = i & 63;
        float a = f[(r0 + r)*C0 + c];
        As[c*264 + 2*r]     = a;
        As[c*264 + 2*r + 1] = a;
        Bs[c*132 + r] = f[(c0 + r)*C0 + c];
    }
    __syncthreads();
    int ty = tid >> 4, tx = tid & 15;
    unsigned long long acc[8][4];
#pragma unroll
    for (int i = 0; i < 8; i++)
#pragma unroll
        for (int j = 0; j < 4; j++) acc[i][j] = 0ULL;

#pragma unroll 4
    for (int k = 0; k < 64; k++) {
        const ulonglong2* apA = (const ulonglong2*)(As + k*264 + 8*ty);
        const ulonglong2* apB = (const ulonglong2*)(As + k*264 + 128 + 8*ty);
        const ulonglong2* bpA = (const ulonglong2*)(Bs + k*132 + 4*tx);
        const ulonglong2* bpB = (const ulonglong2*)(Bs + k*132 + 64 + 4*tx);
        ulonglong2 a0 = apA[0], a1 = apA[1];
        ulonglong2 a2 = apB[0], a3 = apB[1];
        ulonglong2 b0 = bpA[0], b1 = bpB[0];
        unsigned long long av[8] = {a0.x, a0.y, a1.x, a1.y, a2.x, a2.y, a3.x, a3.y};
        unsigned long long bv[4] = {b0.x, b0.y, b1.x, b1.y};
#pragma unroll
        for (int i = 0; i < 8; i++)
#pragma unroll
            for (int j = 0; j < 4; j++)
                acc[i][j] = ffma2(av[i], bv[j], acc[i][j]);
    }
    // normal (row-major) coalesced store
#pragma unroll
    for (int i = 0; i < 8; i++) {
        int rr = r0 + 4*ty + ((i < 4) ? i : (64 + i - 4));
        ulonglong2 s1; s1.x = acc[i][0]; s1.y = acc[i][1];
        ulonglong2 s2; s2.x = acc[i][2]; s2.y = acc[i][3];
        *(ulonglong2*)(S + (size_t)rr*NV + c0 + 4*tx)      = s1;
        *(ulonglong2*)(S + (size_t)rr*NV + c0 + 64 + 4*tx) = s2;
    }
    // mirror: transpose through smem, then coalesced store
    if (by != bx) {
        __syncthreads();
        float* T = As;            // reuse as 128 x (pitch 129) transposed tile
#pragma unroll
        for (int i = 0; i < 8; i++) {
            int rl = 4*ty + ((i < 4) ? i : (64 + i - 4));
#pragma unroll
            for (int j = 0; j < 4; j++) {
                int cl = (j < 2) ? (4*tx + 2*j) : (64 + 4*tx + 2*(j - 2));
                T[cl*129 + rl]       = f2lo(acc[i][j]);
                T[(cl+1)*129 + rl]   = f2hi(acc[i][j]);
            }
        }
        __syncthreads();
        for (int idx = tid; idx < 128*32; idx += 256) {
            int row = idx >> 5, q = idx & 31;
            float4 vv;
            vv.x = T[row*129 + 4*q];
            vv.y = T[row*129 + 4*q + 1];
            vv.z = T[row*129 + 4*q + 2];
            vv.w = T[row*129 + 4*q + 3];
            *(float4*)(S + (size_t)(c0 + row)*NV + r0 + 4*q) = vv;
        }
    }
}

#define TK_INSERT(v, idx)                                          \
    if ((v) > v3) {                                                \
        if ((v) > v2) {                                            \
            v3 = v2; i3 = i2;                                      \
            if ((v) > v1) {                                        \
                v2 = v1; i2 = i1;                                  \
                if ((v) > v0) { v1 = v0; i1 = i0; v0 = (v); i0 = (idx); } \
                else { v1 = (v); i1 = (idx); }                     \
            } else { v2 = (v); i2 = (idx); }                       \
        } else { v3 = (v); i3 = (idx); }                           \
    }

// warp-per-row top-K with per-lane top-4 cache; fused degree counting.
// grid (NV/4, 2), block 128.
__global__ void k_topk3() {
    __shared__ float srow[4][NV];
    int modal = blockIdx.y;
    const float* __restrict__ S = g_sim[modal];
    int* knn = modal ? g_knn2 : g_knn1;
    const int K  = modal ? 13 : 19;
    const int kp = modal ? 5 : 7;       // first kp entries belong to 2 edges
    int warp = threadIdx.x >> 5, lane = threadIdx.x & 31;
    int row = blockIdx.x * 4 + warp;
    float* s = srow[warp];
    int base = lane * 64;
    float v0 = -1e30f, v1 = -1e30f, v2 = -1e30f, v3 = -1e30f;
    int i0 = base, i1 = base, i2 = base, i3 = base;
    {
        const float4* Sr4 = (const float4*)(S + (size_t)row * NV);
#pragma unroll 4
        for (int t = 0; t < 16; t++) {
            float4 x = Sr4[lane*16 + t];
            ((float4*)s)[lane*16 + t] = x;
            int idx = base + t*4;
            TK_INSERT(x.x, idx);
            TK_INSERT(x.y, idx+1);
            TK_INSERT(x.z, idx+2);
            TK_INSERT(x.w, idx+3);
        }
    }
    __syncwarp();
    for (int it = 0; it < K; it++) {
        float m = v0;
#pragma unroll
        for (int off = 16; off; off >>= 1)
            m = fmaxf(m, __shfl_xor_sync(0xffffffffu, m, off));
        unsigned msk = __ballot_sync(0xffffffffu, v0 == m);
        int src = __ffs(msk) - 1;
        int widx = __shfl_sync(0xffffffffu, i0, src);
        if (lane == 0) {
            knn[row*K + it] = widx;
            int vtx = modal ? (NV + widx) : widx;
            atomicAdd(&g_dv[vtx], (it < kp) ? 2 : 1);
        }
        if (lane == src) {
            s[i0] = -1e30f;
            v0 = v1; i0 = i1; v1 = v2; i1 = i2; v2 = v3; i2 = i3;
            v3 = -1e30f; i3 = base;
            if (v0 == -1e30f) {     // cache exhausted: rescan segment
                v0 = v1 = v2 = v3 = -1e30f;
                i0 = i1 = i2 = i3 = base;
#pragma unroll 4
                for (int t = 0; t < 64; t++) {
                    float v = s[base + t];
                    TK_INSERT(v, base + t);
                }
            }
        }
        __syncwarp();
    }
}

// single-block shuffle scan of (dv+1) -> offsets; invsqrt(DV); counter reset
__global__ void k_scan2() {
    __shared__ int wsum[32];
    int tid = threadIdx.x;                 // 1024 threads x 4 elems
    int warp = tid >> 5, lane = tid & 31;
    int base = tid * 4;
    int loc[4]; int s = 0;
#pragma unroll
    for (int i = 0; i < 4; i++) {
        int d = g_dv[base+i] + 1;          // +1 for the inter edge
        loc[i] = d; s += d;
        g_isdv[base+i] = rsqrtf((float)d);
        g_ctr[base+i] = 0;
    }
    int incl = s;
#pragma unroll
    for (int off = 1; off < 32; off <<= 1) {
        int o = __shfl_up_sync(0xffffffffu, incl, off);
        if (lane >= off) incl += o;
    }
    if (lane == 31) wsum[warp] = incl;
    __syncthreads();
    if (warp == 0) {
        int w = wsum[lane];
#pragma unroll
        for (int off = 1; off < 32; off <<= 1) {
            int o = __shfl_up_sync(0xffffffffu, w, off);
            if (lane >= off) w += o;
        }
        wsum[lane] = w;
    }
    __syncthreads();
    int run = (warp ? wsum[warp-1] : 0) + incl - s;
#pragma unroll
    for (int i = 0; i < 4; i++) { g_off[base+i] = run; run += loc[i]; }
    if (tid == 1023) g_off[VV] = wsum[31];
}

// ---- prefix-sharing edge gathers ----
// pair segments: seg 0 = modality-1 centers (k7 edge e=j, k19 edge e=NV+j),
//                seg 1 = modality-2 centers (k5 e=2NV+j, k13 e=3NV+j),
//                seg 2 = inter edges (e=4NV+j, members {j, NV+j}).

// layer-1 edge gather over fp16 raw inputs (256 ch) + adjacency fill.
// grid 3*NV, block 128, 2 ch each.
__global__ void k_edge1p() {
    __shared__ int   mem[19];
    __shared__ float sw[19];
    int bid = blockIdx.x;
    int seg = bid >> 11;
    int j = bid & (NV-1);
    int tid = threadIdx.x;
    int cntA, cntB, eA, eB;
    if (seg == 0) { cntA = 7; cntB = 19; eA = j;      eB = NV + j; }
    else if (seg == 1) { cntA = 5; cntB = 13; eA = 2*NV + j; eB = 3*NV + j; }
    else { cntA = 0; cntB = 2; eA = -1; eB = 4*NV + j; }
    if (tid < cntB) {
        int u;
        if      (seg == 0) u = g_knn1[j*19 + tid];
        else if (seg == 1) u = NV + g_knn2[j*13 + tid];
        else               u = (tid == 0) ? j : NV + j;
        mem[tid] = u;
        sw[tid] = g_isdv[u];
        // fused adjacency fill (was k_fill)
        int slot = atomicAdd(&g_ctr[u], 1);
        g_adj[g_off[u] + slot] = eB;
        if (tid < cntA) {
            int slot2 = atomicAdd(&g_ctr[u], 1);
            g_adj[g_off[u] + slot2] = eA;
        }
    }
    __syncthreads();
    int ch = 2*tid, b = ch >> 6, c = ch & 63;
    float a0 = 0.f, a1 = 0.f;
    float p0 = 0.f, p1 = 0.f;
    for (int t = 0; t < cntB; t++) {
        if (t == cntA) { p0 = a0; p1 = a1; }
        int u = mem[t];
        float s = sw[t];
        const __half2* p = (const __half2*)(g_xh +
            ((u < NV) ? (b*NV + u)*C0 + c : XH2 + (b*NV + u - NV)*C0 + c));
        float2 val = __half22float2(*p);
        a0 += val.x * s;
        a1 += val.y * s;
    }
    float wB = 1.f / ((float)cntB * (float)cntB);
    *(__half2*)(g_z1h + eB*256 + ch) = __floats2half2_rn(wB*a0, wB*a1);
    if (seg < 2) {
        float wA = 1.f / ((float)cntA * (float)cntA);
        *(__half2*)(g_z1h + eA*256 + ch) = __floats2half2_rn(wA*p0, wA*p1);
    }
}

// fused layer-1 vertex gather + linear + relu.
// grid VV/8, block 256 (warp per vertex for gather).
__global__ void k_vl1(const float* __restrict__ W) {
    __shared__ float ts[8][264];       // per-vertex aggregate (256 ch)
    __shared__ float Ws[128*66];
    int tid = threadIdx.x;
    for (int i = tid; i < 128*64; i += 256) {
        int r = i >> 6, c = i & 63;
        Ws[r*66 + c] = W[i];
    }
    int warp = tid >> 5, lane = tid & 31;
    int v = blockIdx.x * 8 + warp;
    {
        int o0 = g_off[v], o1 = g_off[v+1];
        float2 a[4] = {{0,0},{0,0},{0,0},{0,0}};
        for (int i = o0; i < o1; i++) {
            const __half2* z = (const __half2*)(g_z1h + g_adj[i]*256);
#pragma unroll
            for (int q = 0; q < 4; q++) {
                float2 f = __half22float2(z[lane + 32*q]);
                a[q].x += f.x; a[q].y += f.y;
            }
        }
        float s = g_isdv[v];
#pragma unroll
        for (int q = 0; q < 4; q++) {
            ts[warp][2*(lane + 32*q)]     = s * a[q].x;
            ts[warp][2*(lane + 32*q) + 1] = s * a[q].y;
        }
    }
    __syncthreads();
    // linear: thread (b2, o); batches b2 and b2+2
    int b2 = tid >> 7, o = tid & 127;
#pragma unroll
    for (int bq = 0; bq < 2; bq++) {
        int b = b2 + 2*bq;
#pragma unroll
        for (int vi = 0; vi < 8; vi++) {
            unsigned long long acc = 0ULL;
#pragma unroll 8
            for (int fp = 0; fp < 32; fp++)
                acc = ffma2(*(const unsigned long long*)(&ts[vi][b*64 + 2*fp]),
                            *(const unsigned long long*)(Ws + o*66 + 2*fp), acc);
            float y = fmaxf(f2lo(acc) + f2hi(acc), 0.f);
            g_yh[(blockIdx.x*8 + vi)*512 + b*HD + o] = __float2half(y);
        }
    }
}

// layer-2 edge gather over g_yh (512 ch). grid 3*NV, block 128, 4 ch each.
__global__ void k_edge2p() {
    __shared__ int   mem[19];
    __shared__ float sw[19];
    int bid = blockIdx.x;
    int seg = bid >> 11;
    int j = bid & (NV-1);
    int tid = threadIdx.x;
    int cntA, cntB, eA, eB;
    if (seg == 0) { cntA = 7; cntB = 19; eA = j;      eB = NV + j; }
    else if (seg == 1) { cntA = 5; cntB = 13; eA = 2*NV + j; eB = 3*NV + j; }
    else { cntA = 0; cntB = 2; eA = -1; eB = 4*NV + j; }
    if (tid < cntB) {
        int u;
        if      (seg == 0) u = g_knn1[j*19 + tid];
        else if (seg == 1) u = NV + g_knn2[j*13 + tid];
        else               u = (tid == 0) ? j : NV + j;
        mem[tid] = u;
        sw[tid] = g_isdv[u];
    }
    __syncthreads();
    float a0 = 0.f, a1 = 0.f, a2 = 0.f, a3 = 0.f;
    float p0 = 0.f, p1 = 0.f, p2 = 0.f, p3 = 0.f;
    for (int t = 0; t < cntB; t++) {
        if (t == cntA) { p0 = a0; p1 = a1; p2 = a2; p3 = a3; }
        float s = sw[t];
        float4 f = h4_to_f4(*(const uint2*)(g_yh + mem[t]*512 + 4*tid));
        a0 += f.x*s; a1 += f.y*s; a2 += f.z*s; a3 += f.w*s;
    }
    {
        float wB = 1.f / ((float)cntB * (float)cntB);
        __half2 r0 = __floats2half2_rn(wB*a0, wB*a1);
        __half2 r1 = __floats2half2_rn(wB*a2, wB*a3);
        uint2 o; o.x = *(unsigned*)&r0; o.y = *(unsigned*)&r1;
        *(uint2*)(g_z2h + eB*512 + 4*tid) = o;
    }
    if (seg < 2) {
        float wA = 1.f / ((float)cntA * (float)cntA);
        __half2 r0 = __floats2half2_rn(wA*p0, wA*p1);
        __half2 r1 = __floats2half2_rn(wA*p2, wA*p3);
        uint2 o; o.x = *(unsigned*)&r0; o.y = *(unsigned*)&r1;
        *(uint2*)(g_z2h + eA*512 + 4*tid) = o;
    }
}

// layer-2 vertex gather (512 ch). grid VV, block 128, 4 ch each.
__global__ void k_vert2() {
    int v = blockIdx.x;
    int tid = threadIdx.x;
    int o0 = g_off[v], o1 = g_off[v+1];
    float a0 = 0.f, a1 = 0.f, a2 = 0.f, a3 = 0.f;
    int i = o0;
    for (; i + 2 <= o1; i += 2) {
        float4 f = h4_to_f4(*(const uint2*)(g_z2h + g_adj[i]*512   + 4*tid));
        float4 g = h4_to_f4(*(const uint2*)(g_z2h + g_adj[i+1]*512 + 4*tid));
        a0 += f.x + g.x; a1 += f.y + g.y; a2 += f.z + g.z; a3 += f.w + g.w;
    }
    if (i < o1) {
        float4 f = h4_to_f4(*(const uint2*)(g_z2h + g_adj[i]*512 + 4*tid));
        a0 += f.x; a1 += f.y; a2 += f.z; a3 += f.w;
    }
    float s = g_isdv[v];
    *(float4*)(g_u + v*512 + 4*tid) = make_float4(s*a0, s*a1, s*a2, s*a3);
}

// layer-2 linear + relu + permuted store. grid (VV/16, BB), block 128.
__global__ void k_lin2n(const float* __restrict__ W, float* __restrict__ out) {
    __shared__ float Ws[128*66];
    __shared__ float xs[16*132];
    int o = threadIdx.x;
    int b = blockIdx.y;
    int v0 = blockIdx.x * 16;
    for (int i = o; i < 16*128; i += 128) {
        int vi = i >> 7, c = i & 127;
        xs[vi*132 + c] = g_u[(v0+vi)*512 + b*HD + c];
    }
    unsigned long long acc[16];
#pragma unroll
    for (int vi = 0; vi < 16; vi++) acc[vi] = 0ULL;
    for (int half = 0; half < 2; half++) {
        __syncthreads();
        for (int i = o; i < 128*64; i += 128) {
            int r = i >> 6, c = i & 63;
            Ws[r*66 + c] = W[r*HD + half*64 + c];
        }
        __syncthreads();
#pragma unroll 4
        for (int fp = 0; fp < 32; fp++) {
            unsigned long long w = *(const unsigned long long*)(Ws + o*66 + 2*fp);
#pragma unroll
            for (int vi = 0; vi < 16; vi++)
                acc[vi] = ffma2(*(const unsigned long long*)(xs + vi*132 + half*64 + 2*fp), w, acc[vi]);
        }
    }
#pragma unroll
    for (int vi = 0; vi < 16; vi++) {
        float y = fmaxf(f2lo(acc[vi]) + f2hi(acc[vi]), 0.f);
        int v = v0 + vi;
        int h = (v >= NV) ? 1 : 0;
        int n = v - h*NV;
        out[((h*BB + b)*NV + n)*HD + o] = y;
    }
}

// ---------------- launch ----------------
extern "C" void kernel_launch(void* const* d_in, const int* in_sizes, int n_in,
                              void* d_out, int out_size) {
    const float* f1 = (const float*)d_in[0];
    const float* f2 = (const float*)d_in[1];
    const float* W1 = (const float*)d_in[2];
    const float* W2 = (const float*)d_in[3];
    float* out = (float*)d_out;

    cudaFuncSetAttribute(k_sim2, cudaFuncAttributeMaxDynamicSharedMemorySize, SIM_SMEM);

    k_meannorm2<<<VV/8, 256>>>(f1, f2);
    k_sim2<<<dim3(136, 1, 2), 256, SIM_SMEM>>>();
    k_topk3<<<dim3(NV/4, 2), 128>>>();
    k_scan2<<<1, 1024>>>();

    // layer 1:  relu((A x) W1)   (edge gather + adjacency fill fused)
    k_edge1p<<<3*NV, 128>>>();
    k_vl1<<<VV/8, 256>>>(W1);

    // layer 2:  relu((A y) W2)
    k_edge2p<<<3*NV, 128>>>();
    k_vert2<<<VV, 128>>>();
    k_lin2n<<<dim3(VV/16, BB), 128>>>(W2, out);
}

// round 15
// speedup vs baseline: 1.0392x; 1.0392x over previous
#include <cuda_runtime.h>
#include <cuda_fp16.h>
#include <math.h>

#define NV 2048
#define VV 4096           // 2*NV
#define BB 4
#define C0 64
#define HD 128
#define EE (5*NV)         // 10240 edges
#define NNZ (46*NV)       // 94208 memberships
#define XH2 (BB*NV*C0)    // modality-2 offset in g_xh

// ---------------- scratch (device globals; no allocation) ----------------
__device__ float  g_f[VV*C0];      // normalized batch-mean features (fp32)
__device__ __half g_xh[2*BB*NV*C0]; // raw input features (half copy)
__device__ float  g_sim[2][NV*NV];
__device__ int    g_knn1[NV*19];
__device__ int    g_knn2[NV*13];
__device__ int    g_dv[VV];
__device__ float  g_isdv[VV];
__device__ int    g_off[VV+1];
__device__ int    g_ctr[VV];
__device__ int    g_adj[NNZ];
__device__ float  g_t[VV*256];     // layer-1 aggregate (fp32)
__device__ float  g_u[VV*512];     // layer-2 aggregate (fp32)
__device__ __half g_yh[VV*512];    // layer-1 output (half)
__device__ __half g_z1h[EE*256];   // layer-1 edge features (half)
__device__ __half g_z2h[EE*512];   // layer-2 edge features (half)

__device__ __forceinline__ unsigned long long ffma2(unsigned long long a,
                                                    unsigned long long b,
                                                    unsigned long long c) {
    unsigned long long d;
    asm("fma.rn.f32x2 %0, %1, %2, %3;" : "=l"(d) : "l"(a), "l"(b), "l"(c));
    return d;
}
__device__ __forceinline__ float f2lo(unsigned long long x) {
    return __uint_as_float((unsigned)(x & 0xffffffffULL));
}
__device__ __forceinline__ float f2hi(unsigned long long x) {
    return __uint_as_float((unsigned)(x >> 32));
}
__device__ __forceinline__ float4 h4_to_f4(uint2 p) {
    __half2 h0 = *(__half2*)&p.x, h1 = *(__half2*)&p.y;
    float2 f0 = __half22float2(h0), f1 = __half22float2(h1);
    return make_float4(f0.x, f0.y, f1.x, f1.y);
}

// ---------------- kernels ----------------

// batch-mean + L2-normalize (fp32 out for sim) + fp16 raw copy + zero g_dv.
// warp per vertex. grid VV/8, block 256.
__global__ void k_meannorm2(const float* __restrict__ f1, const float* __restrict__ f2) {
    int warp = threadIdx.x >> 5, lane = threadIdx.x & 31;
    int v = blockIdx.x * 8 + warp;
    if (lane == 0) g_dv[v] = 0;
    const float* src; int n; int xoff;
    if (v < NV) { src = f1; n = v;      xoff = 0; }
    else        { src = f2; n = v - NV; xoff = XH2; }
    float m0 = 0.f, m1 = 0.f;
#pragma unroll
    for (int b = 0; b < BB; b++) {
        const float* row = src + (b*NV + n)*C0;
        float r0 = row[lane], r1 = row[lane + 32];
        m0 += r0; m1 += r1;
        g_xh[xoff + (b*NV + n)*C0 + lane]      = __float2half(r0);
        g_xh[xoff + (b*NV + n)*C0 + lane + 32] = __float2half(r1);
    }
    m0 *= 0.25f; m1 *= 0.25f;
    float ss = m0*m0 + m1*m1;
#pragma unroll
    for (int off = 16; off; off >>= 1)
        ss += __shfl_xor_sync(0xffffffffu, ss, off);
    float d = fmaxf(sqrtf(ss), 1e-12f);
    float inv = 1.0f / d;
    g_f[v*C0 + lane]      = m0 * inv;
    g_f[v*C0 + lane + 32] = m1 * inv;
}

// sim = F F^T, symmetric: upper-tri 128x128 block pairs only, fp32 FFMA2.
// mirror via smem transpose. grid (136,1,2), block 256.
#define SIM_SMEM ((64*264 + 64*132) * 4)
__global__ void k_sim2() {
    extern __shared__ float sm[];
    float* As = sm;               // [64][264] A rows duplicated pairwise
    float* Bs = sm + 64*264;      // [64][132]
    int modal = blockIdx.z;
    const float* __restrict__ f = g_f + modal*NV*C0;
    float* __restrict__ S = g_sim[modal];

    // decode upper-tri pair (by <= bx) from linear index
    int li = blockIdx.x, by = 0;
    while (li >= 16 - by) { li -= 16 - by; by++; }
    int bx = by + li;
    int r0 = by * 128, c0 = bx * 128;

    int tid = threadIdx.x;
    for (int i = tid; i < 128*64; i += 256) {
        int r = i >> 6, c = i & 63;
        float a = f[(r0 + r)*C0 + c];
        As[c*264 + 2*r]     = a;
        As[c*264 + 2*r + 1] = a;
        Bs[c*132 + r] = f[(c0 + r)*C0 + c];
    }
    __syncthreads();
    int ty = tid >> 4, tx = tid & 15;
    unsigned long long acc[8][4];
#pragma unroll
    for (int i = 0; i < 8; i++)
#pragma unroll
        for (int j = 0; j < 4; j++) acc[i][j] = 0ULL;

#pragma unroll 4
    for (int k = 0; k < 64; k++) {
        const ulonglong2* apA = (const ulonglong2*)(As + k*264 + 8*ty);
        const ulonglong2* apB = (const ulonglong2*)(As + k*264 + 128 + 8*ty);
        const ulonglong2* bpA = (const ulonglong2*)(Bs + k*132 + 4*tx);
        const ulonglong2* bpB = (const ulonglong2*)(Bs + k*132 + 64 + 4*tx);
        ulonglong2 a0 = apA[0], a1 = apA[1];
        ulonglong2 a2 = apB[0], a3 = apB[1];
        ulonglong2 b0 = bpA[0], b1 = bpB[0];
        unsigned long long av[8] = {a0.x, a0.y, a1.x, a1.y, a2.x, a2.y, a3.x, a3.y};
        unsigned long long bv[4] = {b0.x, b0.y, b1.x, b1.y};
#pragma unroll
        for (int i = 0; i < 8; i++)
#pragma unroll
            for (int j = 0; j < 4; j++)
                acc[i][j] = ffma2(av[i], bv[j], acc[i][j]);
    }
    // normal (row-major) coalesced store
#pragma unroll
    for (int i = 0; i < 8; i++) {
        int rr = r0 + 4*ty + ((i < 4) ? i : (64 + i - 4));
        ulonglong2 s1; s1.x = acc[i][0]; s1.y = acc[i][1];
        ulonglong2 s2; s2.x = acc[i][2]; s2.y = acc[i][3];
        *(ulonglong2*)(S + (size_t)rr*NV + c0 + 4*tx)      = s1;
        *(ulonglong2*)(S + (size_t)rr*NV + c0 + 64 + 4*tx) = s2;
    }
    // mirror: transpose through smem, then coalesced store
    if (by != bx) {
        __syncthreads();
        float* T = As;            // reuse as 128 x (pitch 129) transposed tile
#pragma unroll
        for (int i = 0; i < 8; i++) {
            int rl = 4*ty + ((i < 4) ? i : (64 + i - 4));
#pragma unroll
            for (int j = 0; j < 4; j++) {
                int cl = (j < 2) ? (4*tx + 2*j) : (64 + 4*tx + 2*(j - 2));
                T[cl*129 + rl]       = f2lo(acc[i][j]);
                T[(cl+1)*129 + rl]   = f2hi(acc[i][j]);
            }
        }
        __syncthreads();
        for (int idx = tid; idx < 128*32; idx += 256) {
            int row = idx >> 5, q = idx & 31;
            float4 vv;
            vv.x = T[row*129 + 4*q];
            vv.y = T[row*129 + 4*q + 1];
            vv.z = T[row*129 + 4*q + 2];
            vv.w = T[row*129 + 4*q + 3];
            *(float4*)(S + (size_t)(c0 + row)*NV + r0 + 4*q) = vv;
        }
    }
}

#define TK_INSERT(v, idx)                                          \
    if ((v) > v3) {                                                \
        if ((v) > v2) {                                            \
            v3 = v2; i3 = i2;                                      \
            if ((v) > v1) {                                        \
                v2 = v1; i2 = i1;                                  \
                if ((v) > v0) { v1 = v0; i1 = i0; v0 = (v); i0 = (idx); } \
                else { v1 = (v); i1 = (idx); }                     \
            } else { v2 = (v); i2 = (idx); }                       \
        } else { v3 = (v); i3 = (idx); }                           \
    }

// warp-per-row top-K with per-lane top-4 cache; fused degree counting.
// grid (NV/4, 2), block 128.
__global__ void k_topk3() {
    __shared__ float srow[4][NV];
    int modal = blockIdx.y;
    const float* __restrict__ S = g_sim[modal];
    int* knn = modal ? g_knn2 : g_knn1;
    const int K  = modal ? 13 : 19;
    const int kp = modal ? 5 : 7;       // first kp entries belong to 2 edges
    int warp = threadIdx.x >> 5, lane = threadIdx.x & 31;
    int row = blockIdx.x * 4 + warp;
    float* s = srow[warp];
    int base = lane * 64;
    float v0 = -1e30f, v1 = -1e30f, v2 = -1e30f, v3 = -1e30f;
    int i0 = base, i1 = base, i2 = base, i3 = base;
    {
        const float4* Sr4 = (const float4*)(S + (size_t)row * NV);
#pragma unroll 4
        for (int t = 0; t < 16; t++) {
            float4 x = Sr4[lane*16 + t];
            ((float4*)s)[lane*16 + t] = x;
            int idx = base + t*4;
            TK_INSERT(x.x, idx);
            TK_INSERT(x.y, idx+1);
            TK_INSERT(x.z, idx+2);
            TK_INSERT(x.w, idx+3);
        }
    }
    __syncwarp();
    for (int it = 0; it < K; it++) {
        float m = v0;
#pragma unroll
        for (int off = 16; off; off >>= 1)
            m = fmaxf(m, __shfl_xor_sync(0xffffffffu, m, off));
        unsigned msk = __ballot_sync(0xffffffffu, v0 == m);
        int src = __ffs(msk) - 1;
        int widx = __shfl_sync(0xffffffffu, i0, src);
        if (lane == 0) {
            knn[row*K + it] = widx;
            int vtx = modal ? (NV + widx) : widx;
            atomicAdd(&g_dv[vtx], (it < kp) ? 2 : 1);
        }
        if (lane == src) {
            s[i0] = -1e30f;
            v0 = v1; i0 = i1; v1 = v2; i1 = i2; v2 = v3; i2 = i3;
            v3 = -1e30f; i3 = base;
            if (v0 == -1e30f) {     // cache exhausted: rescan segment
                v0 = v1 = v2 = v3 = -1e30f;
                i0 = i1 = i2 = i3 = base;
#pragma unroll 4
                for (int t = 0; t < 64; t++) {
                    float v = s[base + t];
                    TK_INSERT(v, base + t);
                }
            }
        }
        __syncwarp();
    }
}

// single-block shuffle scan of (dv+1) -> offsets; invsqrt(DV); counter reset
__global__ void k_scan2() {
    __shared__ int wsum[32];
    int tid = threadIdx.x;                 // 1024 threads x 4 elems
    int warp = tid >> 5, lane = tid & 31;
    int base = tid * 4;
    int loc[4]; int s = 0;
#pragma unroll
    for (int i = 0; i < 4; i++) {
        int d = g_dv[base+i] + 1;          // +1 for the inter edge
        loc[i] = d; s += d;
        g_isdv[base+i] = rsqrtf((float)d);
        g_ctr[base+i] = 0;
    }
    int incl = s;
#pragma unroll
    for (int off = 1; off < 32; off <<= 1) {
        int o = __shfl_up_sync(0xffffffffu, incl, off);
        if (lane >= off) incl += o;
    }
    if (lane == 31) wsum[warp] = incl;
    __syncthreads();
    if (warp == 0) {
        int w = wsum[lane];
#pragma unroll
        for (int off = 1; off < 32; off <<= 1) {
            int o = __shfl_up_sync(0xffffffffu, w, off);
            if (lane >= off) w += o;
        }
        wsum[lane] = w;
    }
    __syncthreads();
    int run = (warp ? wsum[warp-1] : 0) + incl - s;
#pragma unroll
    for (int i = 0; i < 4; i++) { g_off[base+i] = run; run += loc[i]; }
    if (tid == 1023) g_off[VV] = wsum[31];
}

// ---- prefix-sharing edge gathers ----
// pair segments: seg 0 = modality-1 centers (k7 edge e=j, k19 edge e=NV+j),
//                seg 1 = modality-2 centers (k5 e=2NV+j, k13 e=3NV+j),
//                seg 2 = inter edges (e=4NV+j, members {j, NV+j}).

// layer-1 edge gather over fp16 raw inputs (256 ch) + fused adjacency fill.
// grid 3*NV, block 128, 2 ch each.
__global__ void k_edge1p() {
    __shared__ int   mem[19];
    __shared__ float sw[19];
    int bid = blockIdx.x;
    int seg = bid >> 11;
    int j = bid & (NV-1);
    int tid = threadIdx.x;
    int cntA, cntB, eA, eB;
    if (seg == 0) { cntA = 7; cntB = 19; eA = j;      eB = NV + j; }
    else if (seg == 1) { cntA = 5; cntB = 13; eA = 2*NV + j; eB = 3*NV + j; }
    else { cntA = 0; cntB = 2; eA = -1; eB = 4*NV + j; }
    if (tid < cntB) {
        int u;
        if      (seg == 0) u = g_knn1[j*19 + tid];
        else if (seg == 1) u = NV + g_knn2[j*13 + tid];
        else               u = (tid == 0) ? j : NV + j;
        mem[tid] = u;
        sw[tid] = g_isdv[u];
        // fused adjacency fill (was k_fill)
        int slot = atomicAdd(&g_ctr[u], 1);
        g_adj[g_off[u] + slot] = eB;
        if (tid < cntA) {
            int slot2 = atomicAdd(&g_ctr[u], 1);
            g_adj[g_off[u] + slot2] = eA;
        }
    }
    __syncthreads();
    int ch = 2*tid, b = ch >> 6, c = ch & 63;
    float a0 = 0.f, a1 = 0.f;
    float p0 = 0.f, p1 = 0.f;
    for (int t = 0; t < cntB; t++) {
        if (t == cntA) { p0 = a0; p1 = a1; }
        int u = mem[t];
        float s = sw[t];
        const __half2* p = (const __half2*)(g_xh +
            ((u < NV) ? (b*NV + u)*C0 + c : XH2 + (b*NV + u - NV)*C0 + c));
        float2 val = __half22float2(*p);
        a0 += val.x * s;
        a1 += val.y * s;
    }
    float wB = 1.f / ((float)cntB * (float)cntB);
    *(__half2*)(g_z1h + eB*256 + ch) = __floats2half2_rn(wB*a0, wB*a1);
    if (seg < 2) {
        float wA = 1.f / ((float)cntA * (float)cntA);
        *(__half2*)(g_z1h + eA*256 + ch) = __floats2half2_rn(wA*p0, wA*p1);
    }
}

// layer-1 vertex gather (256 ch). grid VV, block 128, 2 ch each.
__global__ void k_vert1() {
    int v = blockIdx.x;
    int tid = threadIdx.x;
    int o0 = g_off[v], o1 = g_off[v+1];
    float a0 = 0.f, a1 = 0.f;
    int i = o0;
    for (; i + 2 <= o1; i += 2) {
        __half2 p0 = *(const __half2*)(g_z1h + g_adj[i]*256   + 2*tid);
        __half2 p1 = *(const __half2*)(g_z1h + g_adj[i+1]*256 + 2*tid);
        float2 q0 = __half22float2(p0), q1 = __half22float2(p1);
        a0 += q0.x + q1.x;
        a1 += q0.y + q1.y;
    }
    if (i < o1) {
        float2 q = __half22float2(*(const __half2*)(g_z1h + g_adj[i]*256 + 2*tid));
        a0 += q.x; a1 += q.y;
    }
    float s = g_isdv[v];
    *(float2*)(g_t + v*256 + 2*tid) = make_float2(s*a0, s*a1);
}

// layer-1 linear + relu: yh[v][b*128+o] = relu(sum_c t[v][b*64+c]*W1[o][c])
// grid (VV/16, BB), block 128. packed f32x2. output half.
__global__ void k_lin1n(const float* __restrict__ W) {
    __shared__ float Ws[128*66];
    __shared__ float xs[16*66];
    int o = threadIdx.x;
    int b = blockIdx.y;
    int v0 = blockIdx.x * 16;
    for (int i = o; i < 128*64; i += 128) {
        int r = i >> 6, c = i & 63;
        Ws[r*66 + c] = W[i];
    }
    for (int i = o; i < 16*64; i += 128) {
        int vi = i >> 6, c = i & 63;
        xs[vi*66 + c] = g_t[(v0+vi)*256 + b*64 + c];
    }
    __syncthreads();
    unsigned long long acc[16];
#pragma unroll
    for (int vi = 0; vi < 16; vi++) acc[vi] = 0ULL;
#pragma unroll 4
    for (int fp = 0; fp < 32; fp++) {
        unsigned long long w = *(const unsigned long long*)(Ws + o*66 + 2*fp);
#pragma unroll
        for (int vi = 0; vi < 16; vi++)
            acc[vi] = ffma2(*(const unsigned long long*)(xs + vi*66 + 2*fp), w, acc[vi]);
    }
#pragma unroll
    for (int vi = 0; vi < 16; vi++) {
        float y = fmaxf(f2lo(acc[vi]) + f2hi(acc[vi]), 0.f);
        g_yh[(v0+vi)*512 + b*HD + o] = __float2half(y);
    }
}

// layer-2 edge gather over g_yh (512 ch). grid 3*NV, block 128, 4 ch each.
__global__ void k_edge2p() {
    __shared__ int   mem[19];
    __shared__ float sw[19];
    int bid = blockIdx.x;
    int seg = bid >> 11;
    int j = bid & (NV-1);
    int tid = threadIdx.x;
    int cntA, cntB, eA, eB;
    if (seg == 0) { cntA = 7; cntB = 19; eA = j;      eB = NV + j; }
    else if (seg == 1) { cntA = 5; cntB = 13; eA = 2*NV + j; eB = 3*NV + j; }
    else { cntA = 0; cntB = 2; eA = -1; eB = 4*NV + j; }
    if (tid < cntB) {
        int u;
        if      (seg == 0) u = g_knn1[j*19 + tid];
        else if (seg == 1) u = NV + g_knn2[j*13 + tid];
        else               u = (tid == 0) ? j : NV + j;
        mem[tid] = u;
        sw[tid] = g_isdv[u];
    }
    __syncthreads();
    float a0 = 0.f, a1 = 0.f, a2 = 0.f, a3 = 0.f;
    float p0 = 0.f, p1 = 0.f, p2 = 0.f, p3 = 0.f;
    for (int t = 0; t < cntB; t++) {
        if (t == cntA) { p0 = a0; p1 = a1; p2 = a2; p3 = a3; }
        float s = sw[t];
        float4 f = h4_to_f4(*(const uint2*)(g_yh + mem[t]*512 + 4*tid));
        a0 += f.x*s; a1 += f.y*s; a2 += f.z*s; a3 += f.w*s;
    }
    {
        float wB = 1.f / ((float)cntB * (float)cntB);
        __half2 r0 = __floats2half2_rn(wB*a0, wB*a1);
        __half2 r1 = __floats2half2_rn(wB*a2, wB*a3);
        uint2 o; o.x = *(unsigned*)&r0; o.y = *(unsigned*)&r1;
        *(uint2*)(g_z2h + eB*512 + 4*tid) = o;
    }
    if (seg < 2) {
        float wA = 1.f / ((float)cntA * (float)cntA);
        __half2 r0 = __floats2half2_rn(wA*p0, wA*p1);
        __half2 r1 = __floats2half2_rn(wA*p2, wA*p3);
        uint2 o; o.x = *(unsigned*)&r0; o.y = *(unsigned*)&r1;
        *(uint2*)(g_z2h + eA*512 + 4*tid) = o;
    }
}

// layer-2 vertex gather (512 ch). grid VV, block 128, 4 ch each.
__global__ void k_vert2() {
    int v = blockIdx.x;
    int tid = threadIdx.x;
    int o0 = g_off[v], o1 = g_off[v+1];
    float a0 = 0.f, a1 = 0.f, a2 = 0.f, a3 = 0.f;
    int i = o0;
    for (; i + 2 <= o1; i += 2) {
        float4 f = h4_to_f4(*(const uint2*)(g_z2h + g_adj[i]*512   + 4*tid));
        float4 g = h4_to_f4(*(const uint2*)(g_z2h + g_adj[i+1]*512 + 4*tid));
        a0 += f.x + g.x; a1 += f.y + g.y; a2 += f.z + g.z; a3 += f.w + g.w;
    }
    if (i < o1) {
        float4 f = h4_to_f4(*(const uint2*)(g_z2h + g_adj[i]*512 + 4*tid));
        a0 += f.x; a1 += f.y; a2 += f.z; a3 += f.w;
    }
    float s = g_isdv[v];
    *(float4*)(g_u + v*512 + 4*tid) = make_float4(s*a0, s*a1, s*a2, s*a3);
}

// layer-2 linear + relu + permuted store. grid (VV/16, BB), block 128.
__global__ void k_lin2n(const float* __restrict__ W, float* __restrict__ out) {
    __shared__ float Ws[128*66];
    __shared__ float xs[16*132];
    int o = threadIdx.x;
    int b = blockIdx.y;
    int v0 = blockIdx.x * 16;
    for (int i = o; i < 16*128; i += 128) {
        int vi = i >> 7, c = i & 127;
        xs[vi*132 + c] = g_u[(v0+vi)*512 + b*HD + c];
    }
    unsigned long long acc[16];
#pragma unroll
    for (int vi = 0; vi < 16; vi++) acc[vi] = 0ULL;
    for (int half = 0; half < 2; half++) {
        __syncthreads();
        for (int i = o; i < 128*64; i += 128) {
            int r = i >> 6, c = i & 63;
            Ws[r*66 + c] = W[r*HD + half*64 + c];
        }
        __syncthreads();
#pragma unroll 4
        for (int fp = 0; fp < 32; fp++) {
            unsigned long long w = *(const unsigned long long*)(Ws + o*66 + 2*fp);
#pragma unroll
            for (int vi = 0; vi < 16; vi++)
                acc[vi] = ffma2(*(const unsigned long long*)(xs + vi*132 + half*64 + 2*fp), w, acc[vi]);
        }
    }
#pragma unroll
    for (int vi = 0; vi < 16; vi++) {
        float y = fmaxf(f2lo(acc[vi]) + f2hi(acc[vi]), 0.f);
        int v = v0 + vi;
        int h = (v >= NV) ? 1 : 0;
        int n = v - h*NV;
        out[((h*BB + b)*NV + n)*HD + o] = y;
    }
}

// ---------------- launch ----------------
extern "C" void kernel_launch(void* const* d_in, const int* in_sizes, int n_in,
                              void* d_out, int out_size) {
    const float* f1 = (const float*)d_in[0];
    const float* f2 = (const float*)d_in[1];
    const float* W1 = (const float*)d_in[2];
    const float* W2 = (const float*)d_in[3];
    float* out = (float*)d_out;

    cudaFuncSetAttribute(k_sim2, cudaFuncAttributeMaxDynamicSharedMemorySize, SIM_SMEM);

    k_meannorm2<<<VV/8, 256>>>(f1, f2);
    k_sim2<<<dim3(136, 1, 2), 256, SIM_SMEM>>>();
    k_topk3<<<dim3(NV/4, 2), 128>>>();
    k_scan2<<<1, 1024>>>();

    // layer 1:  relu((A x) W1)   (edge gather + adjacency fill fused)
    k_edge1p<<<3*NV, 128>>>();
    k_vert1<<<VV, 128>>>();
    k_lin1n<<<dim3(VV/16, BB), 128>>>(W1);

    // layer 2:  relu((A y) W2)
    k_edge2p<<<3*NV, 128>>>();
    k_vert2<<<VV, 128>>>();
    k_lin2n<<<dim3(VV/16, BB), 128>>>(W2, out);
}

// round 17
// speedup vs baseline: 1.1192x; 1.0769x over previous
#include <cuda_runtime.h>
#include <cuda_fp16.h>
#include <math.h>

#define NV 2048
#define VV 4096           // 2*NV
#define BB 4
#define C0 64
#define HD 128
#define EE (5*NV)         // 10240 edges
#define NNZ (46*NV)       // 94208 memberships
#define XH2 (BB*NV*C0)    // modality-2 offset in g_xh

// ---------------- scratch (device globals; no allocation) ----------------
__device__ float  g_f[VV*C0];      // normalized batch-mean features (fp32)
__device__ __half g_xh[2*BB*NV*C0]; // raw input features (half copy)
__device__ float  g_sim[2][NV*NV];
__device__ int    g_knn1[NV*19];
__device__ int    g_knn2[NV*13];
__device__ int    g_dv[VV];
__device__ float  g_isdv[VV];
__device__ int    g_off[VV+1];
__device__ int    g_ctr[VV];
__device__ int    g_adj[NNZ];
__device__ float  g_t[VV*256];     // layer-1 aggregate (fp32)
__device__ float  g_u[VV*512];     // layer-2 aggregate (fp32)
__device__ __half g_yh[VV*512];    // layer-1 output (half)
__device__ __half g_z1h[EE*256];   // layer-1 edge features (half)
__device__ __half g_z2h[EE*512];   // layer-2 edge features (half)

__device__ __forceinline__ unsigned long long ffma2(unsigned long long a,
                                                    unsigned long long b,
                                                    unsigned long long c) {
    unsigned long long d;
    asm("fma.rn.f32x2 %0, %1, %2, %3;" : "=l"(d) : "l"(a), "l"(b), "l"(c));
    return d;
}
__device__ __forceinline__ float f2lo(unsigned long long x) {
    return __uint_as_float((unsigned)(x & 0xffffffffULL));
}
__device__ __forceinline__ float f2hi(unsigned long long x) {
    return __uint_as_float((unsigned)(x >> 32));
}
__device__ __forceinline__ float4 h4_to_f4(uint2 p) {
    __half2 h0 = *(__half2*)&p.x, h1 = *(__half2*)&p.y;
    float2 f0 = __half22float2(h0), f1 = __half22float2(h1);
    return make_float4(f0.x, f0.y, f1.x, f1.y);
}

// ---------------- kernels ----------------

// batch-mean + L2-normalize (fp32 out for sim) + fp16 raw copy + zero g_dv.
// warp per vertex. grid VV/8, block 256.
__global__ void k_meannorm2(const float* __restrict__ f1, const float* __restrict__ f2) {
    int warp = threadIdx.x >> 5, lane = threadIdx.x & 31;
    int v = blockIdx.x * 8 + warp;
    if (lane == 0) g_dv[v] = 0;
    const float* src; int n; int xoff;
    if (v < NV) { src = f1; n = v;      xoff = 0; }
    else        { src = f2; n = v - NV; xoff = XH2; }
    float m0 = 0.f, m1 = 0.f;
#pragma unroll
    for (int b = 0; b < BB; b++) {
        const float* row = src + (b*NV + n)*C0;
        float r0 = row[lane], r1 = row[lane + 32];
        m0 += r0; m1 += r1;
        g_xh[xoff + (b*NV + n)*C0 + lane]      = __float2half(r0);
        g_xh[xoff + (b*NV + n)*C0 + lane + 32] = __float2half(r1);
    }
    m0 *= 0.25f; m1 *= 0.25f;
    float ss = m0*m0 + m1*m1;
#pragma unroll
    for (int off = 16; off; off >>= 1)
        ss += __shfl_xor_sync(0xffffffffu, ss, off);
    float d = fmaxf(sqrtf(ss), 1e-12f);
    float inv = 1.0f / d;
    g_f[v*C0 + lane]      = m0 * inv;
    g_f[v*C0 + lane + 32] = m1 * inv;
}

// sim = F F^T, symmetric: upper-tri 128x128 block pairs only, fp32 FFMA2.
// mirror via smem transpose. grid (136,1,2), block 256.
#define SIM_SMEM ((64*264 + 64*132) * 4)
__global__ void k_sim2() {
    extern __shared__ float sm[];
    float* As = sm;               // [64][264] A rows duplicated pairwise
    float* Bs = sm + 64*264;      // [64][132]
    int modal = blockIdx.z;
    const float* __restrict__ f = g_f + modal*NV*C0;
    float* __restrict__ S = g_sim[modal];

    // decode upper-tri pair (by <= bx) from linear index
    int li = blockIdx.x, by = 0;
    while (li >= 16 - by) { li -= 16 - by; by++; }
    int bx = by + li;
    int r0 = by * 128, c0 = bx * 128;

    int tid = threadIdx.x;
    for (int i = tid; i < 128*64; i += 256) {
        int r = i >> 6, c = i & 63;
        float a = f[(r0 + r)*C0 + c];
        As[c*264 + 2*r]     = a;
        As[c*264 + 2*r + 1] = a;
        Bs[c*132 + r] = f[(c0 + r)*C0 + c];
    }
    __syncthreads();
    int ty = tid >> 4, tx = tid & 15;
    unsigned long long acc[8][4];
#pragma unroll
    for (int i = 0; i < 8; i++)
#pragma unroll
        for (int j = 0; j < 4; j++) acc[i][j] = 0ULL;

#pragma unroll 4
    for (int k = 0; k < 64; k++) {
        const ulonglong2* apA = (const ulonglong2*)(As + k*264 + 8*ty);
        const ulonglong2* apB = (const ulonglong2*)(As + k*264 + 128 + 8*ty);
        const ulonglong2* bpA = (const ulonglong2*)(Bs + k*132 + 4*tx);
        const ulonglong2* bpB = (const ulonglong2*)(Bs + k*132 + 64 + 4*tx);
        ulonglong2 a0 = apA[0], a1 = apA[1];
        ulonglong2 a2 = apB[0], a3 = apB[1];
        ulonglong2 b0 = bpA[0], b1 = bpB[0];
        unsigned long long av[8] = {a0.x, a0.y, a1.x, a1.y, a2.x, a2.y, a3.x, a3.y};
        unsigned long long bv[4] = {b0.x, b0.y, b1.x, b1.y};
#pragma unroll
        for (int i = 0; i < 8; i++)
#pragma unroll
            for (int j = 0; j < 4; j++)
                acc[i][j] = ffma2(av[i], bv[j], acc[i][j]);
    }
    // normal (row-major) coalesced store
#pragma unroll
    for (int i = 0; i < 8; i++) {
        int rr = r0 + 4*ty + ((i < 4) ? i : (64 + i - 4));
        ulonglong2 s1; s1.x = acc[i][0]; s1.y = acc[i][1];
        ulonglong2 s2; s2.x = acc[i][2]; s2.y = acc[i][3];
        *(ulonglong2*)(S + (size_t)rr*NV + c0 + 4*tx)      = s1;
        *(ulonglong2*)(S + (size_t)rr*NV + c0 + 64 + 4*tx) = s2;
    }
    // mirror: transpose through smem, then coalesced store
    if (by != bx) {
        __syncthreads();
        float* T = As;            // reuse as 128 x (pitch 129) transposed tile
#pragma unroll
        for (int i = 0; i < 8; i++) {
            int rl = 4*ty + ((i < 4) ? i : (64 + i - 4));
#pragma unroll
            for (int j = 0; j < 4; j++) {
                int cl = (j < 2) ? (4*tx + 2*j) : (64 + 4*tx + 2*(j - 2));
                T[cl*129 + rl]       = f2lo(acc[i][j]);
                T[(cl+1)*129 + rl]   = f2hi(acc[i][j]);
            }
        }
        __syncthreads();
        for (int idx = tid; idx < 128*32; idx += 256) {
            int row = idx >> 5, q = idx & 31;
            float4 vv;
            vv.x = T[row*129 + 4*q];
            vv.y = T[row*129 + 4*q + 1];
            vv.z = T[row*129 + 4*q + 2];
            vv.w = T[row*129 + 4*q + 3];
            *(float4*)(S + (size_t)(c0 + row)*NV + r0 + 4*q) = vv;
        }
    }
}

#define TK_INSERT(v, idx)                                          \
    if ((v) > v3) {                                                \
        if ((v) > v2) {                                            \
            v3 = v2; i3 = i2;                                      \
            if ((v) > v1) {                                        \
                v2 = v1; i2 = i1;                                  \
                if ((v) > v0) { v1 = v0; i1 = i0; v0 = (v); i0 = (idx); } \
                else { v1 = (v); i1 = (idx); }                     \
            } else { v2 = (v); i2 = (idx); }                       \
        } else { v3 = (v); i3 = (idx); }                           \
    }

// warp-per-row top-K with per-lane top-4 cache; fused degree counting.
// grid (NV/4, 2), block 128.
__global__ void k_topk3() {
    __shared__ float srow[4][NV];
    int modal = blockIdx.y;
    const float* __restrict__ S = g_sim[modal];
    int* knn = modal ? g_knn2 : g_knn1;
    const int K  = modal ? 13 : 19;
    const int kp = modal ? 5 : 7;       // first kp entries belong to 2 edges
    int warp = threadIdx.x >> 5, lane = threadIdx.x & 31;
    int row = blockIdx.x * 4 + warp;
    float* s = srow[warp];
    int base = lane * 64;
    float v0 = -1e30f, v1 = -1e30f, v2 = -1e30f, v3 = -1e30f;
    int i0 = base, i1 = base, i2 = base, i3 = base;
    {
        const float4* Sr4 = (const float4*)(S + (size_t)row * NV);
#pragma unroll 4
        for (int t = 0; t < 16; t++) {
            float4 x = Sr4[lane*16 + t];
            ((float4*)s)[lane*16 + t] = x;
            int idx = base + t*4;
            TK_INSERT(x.x, idx);
            TK_INSERT(x.y, idx+1);
            TK_INSERT(x.z, idx+2);
            TK_INSERT(x.w, idx+3);
        }
    }
    __syncwarp();
    for (int it = 0; it < K; it++) {
        float m = v0;
#pragma unroll
        for (int off = 16; off; off >>= 1)
            m = fmaxf(m, __shfl_xor_sync(0xffffffffu, m, off));
        unsigned msk = __ballot_sync(0xffffffffu, v0 == m);
        int src = __ffs(msk) - 1;
        int widx = __shfl_sync(0xffffffffu, i0, src);
        if (lane == 0) {
            knn[row*K + it] = widx;
            int vtx = modal ? (NV + widx) : widx;
            atomicAdd(&g_dv[vtx], (it < kp) ? 2 : 1);
        }
        if (lane == src) {
            s[i0] = -1e30f;
            v0 = v1; i0 = i1; v1 = v2; i1 = i2; v2 = v3; i2 = i3;
            v3 = -1e30f; i3 = base;
            if (v0 == -1e30f) {     // cache exhausted: rescan segment
                v0 = v1 = v2 = v3 = -1e30f;
                i0 = i1 = i2 = i3 = base;
#pragma unroll 4
                for (int t = 0; t < 64; t++) {
                    float v = s[base + t];
                    TK_INSERT(v, base + t);
                }
            }
        }
        __syncwarp();
    }
}

// single-block shuffle scan of (dv+1) -> offsets; invsqrt(DV); counter reset
__global__ void k_scan2() {
    __shared__ int wsum[32];
    int tid = threadIdx.x;                 // 1024 threads x 4 elems
    int warp = tid >> 5, lane = tid & 31;
    int base = tid * 4;
    int loc[4]; int s = 0;
#pragma unroll
    for (int i = 0; i < 4; i++) {
        int d = g_dv[base+i] + 1;          // +1 for the inter edge
        loc[i] = d; s += d;
        g_isdv[base+i] = rsqrtf((float)d);
        g_ctr[base+i] = 0;
    }
    int incl = s;
#pragma unroll
    for (int off = 1; off < 32; off <<= 1) {
        int o = __shfl_up_sync(0xffffffffu, incl, off);
        if (lane >= off) incl += o;
    }
    if (lane == 31) wsum[warp] = incl;
    __syncthreads();
    if (warp == 0) {
        int w = wsum[lane];
#pragma unroll
        for (int off = 1; off < 32; off <<= 1) {
            int o = __shfl_up_sync(0xffffffffu, w, off);
            if (lane >= off) w += o;
        }
        wsum[lane] = w;
    }
    __syncthreads();
    int run = (warp ? wsum[warp-1] : 0) + incl - s;
#pragma unroll
    for (int i = 0; i < 4; i++) { g_off[base+i] = run; run += loc[i]; }
    if (tid == 1023) g_off[VV] = wsum[31];
}

// ---- prefix-sharing edge gathers ----
// pair segments: seg 0 = modality-1 centers (k7 edge e=j, k19 edge e=NV+j),
//                seg 1 = modality-2 centers (k5 e=2NV+j, k13 e=3NV+j),
//                seg 2 = inter edges (e=4NV+j, members {j, NV+j}).

// layer-1 edge gather over fp16 raw inputs (256 ch) + fused adjacency fill.
// grid 3*NV, block 128, 2 ch each.
__global__ void k_edge1p() {
    __shared__ int   mem[19];
    __shared__ float sw[19];
    int bid = blockIdx.x;
    int seg = bid >> 11;
    int j = bid & (NV-1);
    int tid = threadIdx.x;
    int cntA, cntB, eA, eB;
    if (seg == 0) { cntA = 7; cntB = 19; eA = j;      eB = NV + j; }
    else if (seg == 1) { cntA = 5; cntB = 13; eA = 2*NV + j; eB = 3*NV + j; }
    else { cntA = 0; cntB = 2; eA = -1; eB = 4*NV + j; }
    if (tid < cntB) {
        int u;
        if      (seg == 0) u = g_knn1[j*19 + tid];
        else if (seg == 1) u = NV + g_knn2[j*13 + tid];
        else               u = (tid == 0) ? j : NV + j;
        mem[tid] = u;
        sw[tid] = g_isdv[u];
        // fused adjacency fill (was k_fill)
        int slot = atomicAdd(&g_ctr[u], 1);
        g_adj[g_off[u] + slot] = eB;
        if (tid < cntA) {
            int slot2 = atomicAdd(&g_ctr[u], 1);
            g_adj[g_off[u] + slot2] = eA;
        }
    }
    __syncthreads();
    int ch = 2*tid, b = ch >> 6, c = ch & 63;
    float a0 = 0.f, a1 = 0.f;
    float p0 = 0.f, p1 = 0.f;
    for (int t = 0; t < cntB; t++) {
        if (t == cntA) { p0 = a0; p1 = a1; }
        int u = mem[t];
        float s = sw[t];
        const __half2* p = (const __half2*)(g_xh +
            ((u < NV) ? (b*NV + u)*C0 + c : XH2 + (b*NV + u - NV)*C0 + c));
        float2 val = __half22float2(*p);
        a0 += val.x * s;
        a1 += val.y * s;
    }
    float wB = 1.f / ((float)cntB * (float)cntB);
    *(__half2*)(g_z1h + eB*256 + ch) = __floats2half2_rn(wB*a0, wB*a1);
    if (seg < 2) {
        float wA = 1.f / ((float)cntA * (float)cntA);
        *(__half2*)(g_z1h + eA*256 + ch) = __floats2half2_rn(wA*p0, wA*p1);
    }
}

// layer-1 vertex gather (256 ch). grid VV, block 128, 2 ch each.
__global__ void k_vert1() {
    int v = blockIdx.x;
    int tid = threadIdx.x;
    int o0 = g_off[v], o1 = g_off[v+1];
    float a0 = 0.f, a1 = 0.f;
    int i = o0;
    for (; i + 2 <= o1; i += 2) {
        __half2 p0 = *(const __half2*)(g_z1h + g_adj[i]*256   + 2*tid);
        __half2 p1 = *(const __half2*)(g_z1h + g_adj[i+1]*256 + 2*tid);
        float2 q0 = __half22float2(p0), q1 = __half22float2(p1);
        a0 += q0.x + q1.x;
        a1 += q0.y + q1.y;
    }
    if (i < o1) {
        float2 q = __half22float2(*(const __half2*)(g_z1h + g_adj[i]*256 + 2*tid));
        a0 += q.x; a1 += q.y;
    }
    float s = g_isdv[v];
    *(float2*)(g_t + v*256 + 2*tid) = make_float2(s*a0, s*a1);
}

// layer-1 linear + relu, batch-folded: W loaded once per block.
// grid VV/16, block 512 (b = tid>>7, o = tid&127). packed f32x2. output half.
__global__ void k_lin1b(const float* __restrict__ W) {
    __shared__ float Ws[128*66];       // 33.8 KB
    __shared__ float xs[16*264];       // 16 verts x 256 ch (pad 264) = 16.9 KB
    int tid = threadIdx.x;
    int v0 = blockIdx.x * 16;
    for (int i = tid; i < 128*64; i += 512) {
        int r = i >> 6, c = i & 63;
        Ws[r*66 + c] = W[i];
    }
    for (int i = tid; i < 16*256; i += 512) {
        int vi = i >> 8, ch = i & 255;
        xs[vi*264 + ch] = g_t[(v0+vi)*256 + ch];
    }
    __syncthreads();
    int b = tid >> 7, o = tid & 127;
    unsigned long long acc[16];
#pragma unroll
    for (int vi = 0; vi < 16; vi++) acc[vi] = 0ULL;
#pragma unroll 4
    for (int fp = 0; fp < 32; fp++) {
        unsigned long long w = *(const unsigned long long*)(Ws + o*66 + 2*fp);
#pragma unroll
        for (int vi = 0; vi < 16; vi++)
            acc[vi] = ffma2(*(const unsigned long long*)(xs + vi*264 + b*64 + 2*fp), w, acc[vi]);
    }
#pragma unroll
    for (int vi = 0; vi < 16; vi++) {
        float y = fmaxf(f2lo(acc[vi]) + f2hi(acc[vi]), 0.f);
        g_yh[(v0+vi)*512 + b*HD + o] = __float2half(y);
    }
}

// layer-2 edge gather over g_yh (512 ch). grid 3*NV, block 128, 4 ch each.
__global__ void k_edge2p() {
    __shared__ int   mem[19];
    __shared__ float sw[19];
    int bid = blockIdx.x;
    int seg = bid >> 11;
    int j = bid & (NV-1);
    int tid = threadIdx.x;
    int cntA, cntB, eA, eB;
    if (seg == 0) { cntA = 7; cntB = 19; eA = j;      eB = NV + j; }
    else if (seg == 1) { cntA = 5; cntB = 13; eA = 2*NV + j; eB = 3*NV + j; }
    else { cntA = 0; cntB = 2; eA = -1; eB = 4*NV + j; }
    if (tid < cntB) {
        int u;
        if      (seg == 0) u = g_knn1[j*19 + tid];
        else if (seg == 1) u = NV + g_knn2[j*13 + tid];
        else               u = (tid == 0) ? j : NV + j;
        mem[tid] = u;
        sw[tid] = g_isdv[u];
    }
    __syncthreads();
    float a0 = 0.f, a1 = 0.f, a2 = 0.f, a3 = 0.f;
    float p0 = 0.f, p1 = 0.f, p2 = 0.f, p3 = 0.f;
    for (int t = 0; t < cntB; t++) {
        if (t == cntA) { p0 = a0; p1 = a1; p2 = a2; p3 = a3; }
        float s = sw[t];
        float4 f = h4_to_f4(*(const uint2*)(g_yh + mem[t]*512 + 4*tid));
        a0 += f.x*s; a1 += f.y*s; a2 += f.z*s; a3 += f.w*s;
    }
    {
        float wB = 1.f / ((float)cntB * (float)cntB);
        __half2 r0 = __floats2half2_rn(wB*a0, wB*a1);
        __half2 r1 = __floats2half2_rn(wB*a2, wB*a3);
        uint2 o; o.x = *(unsigned*)&r0; o.y = *(unsigned*)&r1;
        *(uint2*)(g_z2h + eB*512 + 4*tid) = o;
    }
    if (seg < 2) {
        float wA = 1.f / ((float)cntA * (float)cntA);
        __half2 r0 = __floats2half2_rn(wA*p0, wA*p1);
        __half2 r1 = __floats2half2_rn(wA*p2, wA*p3);
        uint2 o; o.x = *(unsigned*)&r0; o.y = *(unsigned*)&r1;
        *(uint2*)(g_z2h + eA*512 + 4*tid) = o;
    }
}

// layer-2 vertex gather (512 ch). grid VV, block 128, 4 ch each.
__global__ void k_vert2() {
    int v = blockIdx.x;
    int tid = threadIdx.x;
    int o0 = g_off[v], o1 = g_off[v+1];
    float a0 = 0.f, a1 = 0.f, a2 = 0.f, a3 = 0.f;
    int i = o0;
    for (; i + 2 <= o1; i += 2) {
        float4 f = h4_to_f4(*(const uint2*)(g_z2h + g_adj[i]*512   + 4*tid));
        float4 g = h4_to_f4(*(const uint2*)(g_z2h + g_adj[i+1]*512 + 4*tid));
        a0 += f.x + g.x; a1 += f.y + g.y; a2 += f.z + g.z; a3 += f.w + g.w;
    }
    if (i < o1) {
        float4 f = h4_to_f4(*(const uint2*)(g_z2h + g_adj[i]*512 + 4*tid));
        a0 += f.x; a1 += f.y; a2 += f.z; a3 += f.w;
    }
    float s = g_isdv[v];
    *(float4*)(g_u + v*512 + 4*tid) = make_float4(s*a0, s*a1, s*a2, s*a3);
}

// layer-2 linear + relu + permuted store, batch-folded.
// grid VV/16, block 512. W loaded once per block (two 64-col halves).
__global__ void k_lin2b(const float* __restrict__ W, float* __restrict__ out) {
    __shared__ float Ws[128*66];       // 33.8 KB (one half of W)
    __shared__ float xs[16*520];       // 16 verts x 512 ch (pad 520) = 33.3 KB
    int tid = threadIdx.x;
    int v0 = blockIdx.x * 16;
    for (int i = tid; i < 16*512; i += 512) {
        int vi = i >> 9, ch = i & 511;
        xs[vi*520 + ch] = g_u[(v0+vi)*512 + ch];
    }
    int b = tid >> 7, o = tid & 127;
    unsigned long long acc[16];
#pragma unroll
    for (int vi = 0; vi < 16; vi++) acc[vi] = 0ULL;
    for (int half = 0; half < 2; half++) {
        __syncthreads();
        for (int i = tid; i < 128*64; i += 512) {
            int r = i >> 6, c = i & 63;
            Ws[r*66 + c] = W[r*HD + half*64 + c];
        }
        __syncthreads();
#pragma unroll 4
        for (int fp = 0; fp < 32; fp++) {
            unsigned long long w = *(const unsigned long long*)(Ws + o*66 + 2*fp);
#pragma unroll
            for (int vi = 0; vi < 16; vi++)
                acc[vi] = ffma2(*(const unsigned long long*)(xs + vi*520 + b*HD + half*64 + 2*fp), w, acc[vi]);
        }
    }
#pragma unroll
    for (int vi = 0; vi < 16; vi++) {
        float y = fmaxf(f2lo(acc[vi]) + f2hi(acc[vi]), 0.f);
        int v = v0 + vi;
        int h = (v >= NV) ? 1 : 0;
        int n = v - h*NV;
        out[((h*BB + b)*NV + n)*HD + o] = y;
    }
}

// ---------------- launch ----------------
extern "C" void kernel_launch(void* const* d_in, const int* in_sizes, int n_in,
                              void* d_out, int out_size) {
    const float* f1 = (const float*)d_in[0];
    const float* f2 = (const float*)d_in[1];
    const float* W1 = (const float*)d_in[2];
    const float* W2 = (const float*)d_in[3];
    float* out = (float*)d_out;

    cudaFuncSetAttribute(k_sim2, cudaFuncAttributeMaxDynamicSharedMemorySize, SIM_SMEM);

    k_meannorm2<<<VV/8, 256>>>(f1, f2);
    k_sim2<<<dim3(136, 1, 2), 256, SIM_SMEM>>>();
    k_topk3<<<dim3(NV/4, 2), 128>>>();
    k_scan2<<<1, 1024>>>();

    // layer 1:  relu((A x) W1)   (edge gather + adjacency fill fused)
    k_edge1p<<<3*NV, 128>>>();
    k_vert1<<<VV, 128>>>();
    k_lin1b<<<VV/16, 512>>>(W1);

    // layer 2:  relu((A y) W2)
    k_edge2p<<<3*NV, 128>>>();
    k_vert2<<<VV, 128>>>();
    k_lin2b<<<VV/16, 512>>>(W2, out);
}